// round 10
// baseline (speedup 1.0000x reference)
#include <cuda_runtime.h>
#include <cuda_bf16.h>

#define VOCAB  32000
#define NLABEL 16
#define NSTATE 64
#define BATCH  512
#define MAXLEN 512

typedef unsigned long long ull;

// Packed f32x2 ops (sm_103a; SASS FFMA2 — PTX-only path).
#define FMA2(d, a, b, c) \
    asm("fma.rn.f32x2 %0, %1, %2, %3;" : "=l"(d) : "l"(a), "l"(b), "l"(c))
#define ADD2(d, a, b) \
    asm("add.rn.f32x2 %0, %1, %2;" : "=l"(d) : "l"(a), "l"(b))

// Precomputed tables (device globals: no allocation allowed).
// g_Tpack float layout: Texp[r][i] stored at (i>>1)*128 + r*2 + (i&1).
// As 8-byte pairs: ull index jv*64 + r = (Texp[r][2jv], Texp[r][2jv+1]).
__device__ __align__(16) float g_Tpack[NSTATE * NSTATE];
__device__ float g_Oexp[NLABEL * NSTATE];   // [l*64 + s] = softmax(output[l,:])[s]
__device__ float g_lse [VOCAB];             // logsumexp(emb[v,:])

// ---------------------------------------------------------------------------
// Fused prep: blocks [0,40) do row-softmax (2 rows/block: 64+16 rows total);
// blocks [40, 40+VOCAB/4) do per-vocab-row logsumexp (4 rows/block).
// ---------------------------------------------------------------------------
__global__ void prep_all_kernel(const float* __restrict__ transition,
                                const float* __restrict__ output,
                                const float* __restrict__ emb) {
    const int blk = blockIdx.x;
    if (blk < 40) {
        const int half = threadIdx.x >> 6;     // which row in this block
        const int i    = threadIdx.x & 63;     // state index within row
        const int r    = blk * 2 + half;       // global row 0..79
        const float* src = (r < NSTATE) ? (transition + r * NSTATE)
                                        : (output + (r - NSTATE) * NSTATE);
        float v = src[i];

        __shared__ float shm[4];
        __shared__ float shs[4];

        float m = v;
        #pragma unroll
        for (int d = 16; d; d >>= 1) m = fmaxf(m, __shfl_xor_sync(0xffffffffu, m, d));
        if ((threadIdx.x & 31) == 0) shm[threadIdx.x >> 5] = m;
        __syncthreads();
        m = fmaxf(shm[half * 2], shm[half * 2 + 1]);

        float e = expf(v - m);
        float s = e;
        #pragma unroll
        for (int d = 16; d; d >>= 1) s += __shfl_xor_sync(0xffffffffu, s, d);
        if ((threadIdx.x & 31) == 0) shs[threadIdx.x >> 5] = s;
        __syncthreads();
        s = shs[half * 2] + shs[half * 2 + 1];

        const float val = e / s;
        if (r < NSTATE) g_Tpack[(i >> 1) * 128 + r * 2 + (i & 1)] = val;
        else            g_Oexp[(r - NSTATE) * NSTATE + i] = val;
    } else {
        const int gw   = (blk - 40) * 4 + (threadIdx.x >> 5);
        const int lane = threadIdx.x & 31;
        if (gw >= VOCAB) return;
        const float* row = emb + gw * NSTATE;
        float s = expf(row[lane]) + expf(row[lane + 32]);
        #pragma unroll
        for (int d = 16; d; d >>= 1) s += __shfl_xor_sync(0xffffffffu, s, d);
        if (lane == 0) g_lse[gw] = logf(s);
    }
}

// ---------------------------------------------------------------------------
// Main: one block (128 threads = 4 warps) per batch element.
// 2x2 split: warps {0,1} compute ODD steps, warps {2,3} EVEN steps; within a
// pair, warp h owns states [h*32, h*32+32) (one state per lane, transition
// row K-packed as 32 f32x2 pairs -> 32 FFMA2 per lane per step).
// Buffers are parity-static: odd steps read G0/write G1, even read G1/write
// G0. One __syncthreads per step (all 4 warps, uniform trip count).
// This puts 3.46 warps on EVERY SMSP (vs all on SMSP0 before), quartering
// the per-SMSP FFMA2 issue load. Unnormalized recurrence, renorm every 64
// steps (even t -> handled by pair 1; off accumulated in warp 2).
// ---------------------------------------------------------------------------
__global__ void __launch_bounds__(128) hmm_forward_kernel(
    const int*   __restrict__ sentences,
    const int*   __restrict__ length,
    const float* __restrict__ emb,
    float*       __restrict__ out)
{
    const int tid  = threadIdx.x;
    const int w    = tid >> 5;        // warp 0..3  -> SMSP w
    const int lane = tid & 31;
    const int h    = w & 1;           // state half within pair
    const int prty = (w >> 1) ? 0 : 1;// warps 0,1 compute odd t; 2,3 even t
    const int s    = h * 32 + lane;   // my state
    const int b    = blockIdx.x;

    __shared__ __align__(16) float G0[NSTATE];
    __shared__ __align__(16) float G1[NSTATE];
    __shared__ int   toks[MAXLEN + 5];
    __shared__ float off_sh;

    const int  L    = length[b];
    const int  Lm1  = L - 1;
    const int* sent = sentences + b * MAXLEN;

    // Stage tokens pre-clamped: toks[i] = sent[min(i, L-1)], i < L+5.
    for (int i = tid; i < L + 5; i += 128) toks[i] = __ldg(&sent[min(i, Lm1)]);

    // Transition row for my state, K-packed: T2[jv] = (T[s][2jv], T[s][2jv+1]).
    ull T2[NSTATE / 2];
    {
        const ull* Tp = reinterpret_cast<const ull*>(g_Tpack);
        #pragma unroll
        for (int jv = 0; jv < NSTATE / 2; ++jv)
            T2[jv] = __ldg(&Tp[jv * 64 + s]);
    }

    // ---- t = 0 init (threads 0..63 cover all states) ----
    const int tok0 = __ldg(&sent[0]);
    if (tid < NSTATE) G0[tid] = __expf(__ldg(&emb[tok0 * NSTATE + tid]));
    __syncthreads();   // toks + G0 visible block-wide

    // Parity-static buffers: odd steps read G0 -> write G1; even G1 -> G0.
    const float* Gsrc = (prty & 1) ? G0 : G1;
    float*       Gdst = (prty & 1) ? G1 : G0;

    // My first step and 2-deep prefetch of MY emission values (stride 2).
    const int first = (prty & 1) ? 1 : 2;
    float r1 = __ldg(&emb[toks[first]     * NSTATE + s]);
    float r2 = __ldg(&emb[toks[first + 2] * NSTATE + s]);

    float off = 0.f;

    for (int t = 1; t < L; ++t) {
        if ((t & 1) == (first & 1)) {      // my pair's step (warp-uniform)
            float e = __expf(r1);
            r1 = r2;
            r2 = __ldg(&emb[toks[t + 4] * NSTATE + s]);

            if ((t & 63) == 0) {           // renorm: only even steps hit this
                const float g0 = Gsrc[0];
                float c;
                asm("rcp.approx.f32 %0, %1;" : "=f"(c) : "f"(g0));
                e *= c;
                if (h == 0) off += __logf(g0);   // only warp 2 accumulates
            }

            // 64-wide matvec for my state: 16 broadcast LDS.128 + 32 FFMA2.
            const ulonglong2* Gv = reinterpret_cast<const ulonglong2*>(Gsrc);
            ull a0 = 0ull, a1 = 0ull;
            #pragma unroll
            for (int jv = 0; jv < 16; ++jv) {
                const ulonglong2 g = Gv[jv];
                FMA2(a0, T2[2 * jv + 0], g.x, a0);
                FMA2(a1, T2[2 * jv + 1], g.y, a1);
            }
            ull as;
            ADD2(as, a0, a1);
            float lo, hi;
            asm("mov.b64 {%0, %1}, %2;" : "=f"(lo), "=f"(hi) : "l"(as));
            Gdst[s] = (lo + hi) * e;
        }
        __syncthreads();
    }

    // Publish off (warp 2 holds the only nonzero copy; renorm t are even).
    if (w == 2 && lane == 0) off_sh = off;

    // ---- emission-normalizer sum S (warp 0, overlaps with off publish) ----
    float S = 0.f;
    if (w == 0) {
        for (int i = lane; i < L; i += 32) S += __ldg(&g_lse[toks[i]]);
        #pragma unroll
        for (int d = 16; d; d >>= 1) S += __shfl_xor_sync(0xffffffffu, S, d);
    }
    __syncthreads();

    // ---- readout: warp 0 lanes 0..15, one label each ----
    if (w == 0 && lane < NLABEL) {
        const float* Gf = (Lm1 & 1) ? G1 : G0;   // buffer written by step L-1
        const float* O  = g_Oexp + lane * NSTATE;
        float a0 = 0.f, a1 = 0.f, a2 = 0.f, a3 = 0.f;
        #pragma unroll
        for (int j4 = 0; j4 < NSTATE / 4; ++j4) {
            a0 = fmaf(__ldg(&O[4 * j4 + 0]), Gf[4 * j4 + 0], a0);
            a1 = fmaf(__ldg(&O[4 * j4 + 1]), Gf[4 * j4 + 1], a1);
            a2 = fmaf(__ldg(&O[4 * j4 + 2]), Gf[4 * j4 + 2], a2);
            a3 = fmaf(__ldg(&O[4 * j4 + 3]), Gf[4 * j4 + 3], a3);
        }
        out[b * NLABEL + lane] = __logf((a0 + a1) + (a2 + a3)) + off_sh - S;
    }
}

// ---------------------------------------------------------------------------
extern "C" void kernel_launch(void* const* d_in, const int* in_sizes, int n_in,
                              void* d_out, int out_size) {
    const int*   sentences  = nullptr;
    const int*   length     = nullptr;
    const float* emb        = nullptr;
    const float* transition = nullptr;
    const float* output     = nullptr;

    for (int i = 0; i < n_in; ++i) {
        switch (in_sizes[i]) {
            case BATCH * MAXLEN:   sentences  = (const int*)  d_in[i]; break;
            case BATCH:            length     = (const int*)  d_in[i]; break;
            case VOCAB * NSTATE:   emb        = (const float*)d_in[i]; break;
            case NSTATE * NSTATE:  transition = (const float*)d_in[i]; break;
            case NLABEL * NSTATE:  output     = (const float*)d_in[i]; break;
            default: break;
        }
    }

    prep_all_kernel<<<40 + VOCAB / 4, 128>>>(transition, output, emb);
    hmm_forward_kernel<<<BATCH, 128>>>(sentences, length, emb, (float*)d_out);
}

// round 11
// speedup vs baseline: 1.0799x; 1.0799x over previous
#include <cuda_runtime.h>
#include <cuda_bf16.h>

#define VOCAB  32000
#define NLABEL 16
#define NSTATE 64
#define BATCH  512
#define MAXLEN 512

typedef unsigned long long ull;

// Packed f32x2 ops (sm_103a; SASS FFMA2 — PTX-only path).
#define FMA2(d, a, b, c) \
    asm("fma.rn.f32x2 %0, %1, %2, %3;" : "=l"(d) : "l"(a), "l"(b), "l"(c))
#define ADD2(d, a, b) \
    asm("add.rn.f32x2 %0, %1, %2;" : "=l"(d) : "l"(a), "l"(b))

// Precomputed tables (device globals: no allocation allowed).
// g_Tpack float layout: Texp[r][i] stored at (i>>1)*128 + r*2 + (i&1).
// As 8-byte pairs: ull index jv*64 + r = (Texp[r][2jv], Texp[r][2jv+1]).
__device__ __align__(16) float g_Tpack[NSTATE * NSTATE];
__device__ float g_Oexp[NLABEL * NSTATE];   // [l*64 + s] = softmax(output[l,:])[s]
__device__ float g_lse [VOCAB];             // logsumexp(emb[v,:])

// ---------------------------------------------------------------------------
// Fused prep: blocks [0,40) do row-softmax (2 rows/block: 64+16 rows total);
// blocks [40, 40+VOCAB/4) do per-vocab-row logsumexp (4 rows/block).
// ---------------------------------------------------------------------------
__global__ void prep_all_kernel(const float* __restrict__ transition,
                                const float* __restrict__ output,
                                const float* __restrict__ emb) {
    const int blk = blockIdx.x;
    if (blk < 40) {
        const int half = threadIdx.x >> 6;     // which row in this block
        const int i    = threadIdx.x & 63;     // state index within row
        const int r    = blk * 2 + half;       // global row 0..79
        const float* src = (r < NSTATE) ? (transition + r * NSTATE)
                                        : (output + (r - NSTATE) * NSTATE);
        float v = src[i];

        __shared__ float shm[4];
        __shared__ float shs[4];

        float m = v;
        #pragma unroll
        for (int d = 16; d; d >>= 1) m = fmaxf(m, __shfl_xor_sync(0xffffffffu, m, d));
        if ((threadIdx.x & 31) == 0) shm[threadIdx.x >> 5] = m;
        __syncthreads();
        m = fmaxf(shm[half * 2], shm[half * 2 + 1]);

        float e = expf(v - m);
        float s = e;
        #pragma unroll
        for (int d = 16; d; d >>= 1) s += __shfl_xor_sync(0xffffffffu, s, d);
        if ((threadIdx.x & 31) == 0) shs[threadIdx.x >> 5] = s;
        __syncthreads();
        s = shs[half * 2] + shs[half * 2 + 1];

        const float val = e / s;
        if (r < NSTATE) g_Tpack[(i >> 1) * 128 + r * 2 + (i & 1)] = val;
        else            g_Oexp[(r - NSTATE) * NSTATE + i] = val;
    } else {
        const int gw   = (blk - 40) * 4 + (threadIdx.x >> 5);
        const int lane = threadIdx.x & 31;
        if (gw >= VOCAB) return;
        const float* row = emb + gw * NSTATE;
        float s = expf(row[lane]) + expf(row[lane + 32]);
        #pragma unroll
        for (int d = 16; d; d >>= 1) s += __shfl_xor_sync(0xffffffffu, s, d);
        if (lane == 0) g_lse[gw] = logf(s);
    }
}

// ---------------------------------------------------------------------------
// Main: 256 blocks x 64 threads; each of the 2 warps in a block independently
// runs one batch (b = 2*blockIdx.x + w). NO inter-warp coupling, NO
// __syncthreads. Step body, prefetch, renorm, epilogue are byte-identical to
// the 96.7us champion; only SMEM gains a per-warp dimension. With 1.73
// blocks/SM, warps land on SMSP0 and SMSP1 at ~1.73 warps each (vs all on
// SMSP0 before), halving per-SMSP FFMA2 issue pressure while keeping enough
// co-residency to hide the serial chain.
// ---------------------------------------------------------------------------
__global__ void __launch_bounds__(64) hmm_forward_kernel(
    const int*   __restrict__ sentences,
    const int*   __restrict__ length,
    const float* __restrict__ emb,
    float*       __restrict__ out)
{
    const int w    = threadIdx.x >> 5;           // warp 0..1 within block
    const int lane = threadIdx.x & 31;
    const int b    = blockIdx.x * 2 + w;         // batch for this warp

    __shared__ __align__(16) float Gsh[2][2][NSTATE];
    __shared__ int toksh[2][MAXLEN + 3];

    float (*G)[NSTATE] = Gsh[w];
    int*  toks         = toksh[w];

    const int  L    = length[b];
    const int  Lm1  = L - 1;
    const int* sent = sentences + b * MAXLEN;

    // Stage tokens pre-clamped: toks[i] = sent[min(i, L-1)] for i < L+3.
    for (int i = lane; i < L + 3; i += 32) toks[i] = __ldg(&sent[min(i, Lm1)]);

    // Transition rows for states s0=2*lane, s1=2*lane+1:
    // TA[jv] = (Texp[s0][2jv], Texp[s0][2jv+1]), TB likewise for s1.
    ull TA[NSTATE / 2], TB[NSTATE / 2];
    {
        const ulonglong2* Tp = reinterpret_cast<const ulonglong2*>(g_Tpack);
        #pragma unroll
        for (int jv = 0; jv < NSTATE / 2; ++jv) {
            const ulonglong2 p = __ldg(&Tp[jv * 32 + lane]);   // ull idx jv*64+2l
            TA[jv] = p.x;
            TB[jv] = p.y;
        }
    }

    // ---- t = 0 ----
    const int tok0 = __ldg(&sent[0]);
    const float2 raw0 = *reinterpret_cast<const float2*>(&emb[tok0 * NSTATE + 2 * lane]);
    *reinterpret_cast<float2*>(&G[0][2 * lane]) =
        make_float2(__expf(raw0.x), __expf(raw0.y));
    __syncwarp();   // G[0] + toks visible warp-wide

    // 3-deep emission-row prefetch (toks pre-clamped: always valid loads).
    float2 r1 = *reinterpret_cast<const float2*>(&emb[toks[1] * NSTATE + 2 * lane]);
    float2 r2 = *reinterpret_cast<const float2*>(&emb[toks[2] * NSTATE + 2 * lane]);
    float2 r3 = *reinterpret_cast<const float2*>(&emb[toks[3] * NSTATE + 2 * lane]);

    float off = 0.f;
    int   buf = 0;

    for (int t = 1; t < L; ++t) {
        float eA = __expf(r1.x);
        float eB = __expf(r1.y);
        r1 = r2; r2 = r3;
        r3 = *reinterpret_cast<const float2*>(&emb[toks[t + 3] * NSTATE + 2 * lane]);

        if ((t & 63) == 0) {       // periodic renormalization (uniform branch)
            const float g0 = G[buf][0];
            float c;
            asm("rcp.approx.f32 %0, %1;" : "=f"(c) : "f"(g0));
            eA *= c;
            eB *= c;
            off += __logf(g0);
        }

        // Two 64-wide matvecs (states s0, s1) from shared G, packed f32x2.
        const ulonglong2* Gv = reinterpret_cast<const ulonglong2*>(G[buf]);
        ull a0 = 0ull, a1 = 0ull, b0 = 0ull, b1 = 0ull;
        #pragma unroll
        for (int jv = 0; jv < 16; ++jv) {
            const ulonglong2 g = Gv[jv];
            FMA2(a0, TA[2 * jv + 0], g.x, a0);
            FMA2(b0, TB[2 * jv + 0], g.x, b0);
            FMA2(a1, TA[2 * jv + 1], g.y, a1);
            FMA2(b1, TB[2 * jv + 1], g.y, b1);
        }
        ull as, bs;
        ADD2(as, a0, a1);
        ADD2(bs, b0, b1);
        float alo, ahi, blo, bhi;
        asm("mov.b64 {%0, %1}, %2;" : "=f"(alo), "=f"(ahi) : "l"(as));
        asm("mov.b64 {%0, %1}, %2;" : "=f"(blo), "=f"(bhi) : "l"(bs));
        const float GnA = (alo + ahi) * eA;
        const float GnB = (blo + bhi) * eB;

        buf ^= 1;
        *reinterpret_cast<float2*>(&G[buf][2 * lane]) = make_float2(GnA, GnB);
        __syncwarp();
    }

    // ---- emission-normalizer sum S = sum_{t<L} lse[tok_t] ----
    float S = 0.f;
    for (int i = lane; i < L; i += 32) S += __ldg(&g_lse[toks[i]]);
    #pragma unroll
    for (int d = 16; d; d >>= 1) S += __shfl_xor_sync(0xffffffffu, S, d);

    // ---- readout: lanes 0..15 each compute one label ----
    if (lane < NLABEL) {
        const float* O  = g_Oexp + lane * NSTATE;
        const float* Gf = G[buf];
        float a0 = 0.f, a1 = 0.f, a2 = 0.f, a3 = 0.f;
        #pragma unroll
        for (int j4 = 0; j4 < NSTATE / 4; ++j4) {
            a0 = fmaf(__ldg(&O[4 * j4 + 0]), Gf[4 * j4 + 0], a0);
            a1 = fmaf(__ldg(&O[4 * j4 + 1]), Gf[4 * j4 + 1], a1);
            a2 = fmaf(__ldg(&O[4 * j4 + 2]), Gf[4 * j4 + 2], a2);
            a3 = fmaf(__ldg(&O[4 * j4 + 3]), Gf[4 * j4 + 3], a3);
        }
        out[b * NLABEL + lane] = __logf((a0 + a1) + (a2 + a3)) + off - S;
    }
}

// ---------------------------------------------------------------------------
extern "C" void kernel_launch(void* const* d_in, const int* in_sizes, int n_in,
                              void* d_out, int out_size) {
    const int*   sentences  = nullptr;
    const int*   length     = nullptr;
    const float* emb        = nullptr;
    const float* transition = nullptr;
    const float* output     = nullptr;

    for (int i = 0; i < n_in; ++i) {
        switch (in_sizes[i]) {
            case BATCH * MAXLEN:   sentences  = (const int*)  d_in[i]; break;
            case BATCH:            length     = (const int*)  d_in[i]; break;
            case VOCAB * NSTATE:   emb        = (const float*)d_in[i]; break;
            case NSTATE * NSTATE:  transition = (const float*)d_in[i]; break;
            case NLABEL * NSTATE:  output     = (const float*)d_in[i]; break;
            default: break;
        }
    }

    prep_all_kernel<<<40 + VOCAB / 4, 128>>>(transition, output, emb);
    hmm_forward_kernel<<<BATCH / 2, 64>>>(sentences, length, emb, (float*)d_out);
}